// round 2
// baseline (speedup 1.0000x reference)
#include <cuda_runtime.h>
#include <cstdint>

// Problem constants (from reference): T=512, B=1024, DK=128, H=256, NH=4
#define T_MAX 512
#define BSZ   1024
#define DKDIM 128
#define VDIM  512      // 2*H
#define NHEAD 4
#define OUTD  512      // 2*H
#define KIN   2048     // NH*2*H

// 8 MB scratch for res [B][NH][VDIM] = res_flat [B][KIN]
__device__ float g_res[(size_t)BSZ * KIN];

// ---------------------------------------------------------------------------
// Kernel A: fused (keys*rpe) @ q^T -> softmax over slots -> weighted sum of vals
// One CTA per batch element b. 256 threads.
// ---------------------------------------------------------------------------
__global__ __launch_bounds__(256) void dnd_attn_kernel(
    const float* __restrict__ keys,   // [T][B][DK]
    const float* __restrict__ vals,   // [T][B][VDIM]
    const float* __restrict__ rpe,    // [T][B]
    const float* __restrict__ query,  // [B][NH][DK]
    const int*   __restrict__ min_step_p)
{
    __shared__ __align__(16) float sQ[NHEAD * DKDIM];     // 2 KB
    __shared__ __align__(16) float sA[NHEAD][T_MAX];      // 8 KB, head-major

    const int b    = blockIdx.x;
    const int tid  = threadIdx.x;
    const int warp = tid >> 5;
    const int lane = tid & 31;
    const int M    = min_step_p[0];

    // --- load query heads to smem ---
    for (int i = tid; i < NHEAD * DKDIM; i += 256)
        sQ[i] = query[(size_t)b * NHEAD * DKDIM + i];
    __syncthreads();

    // --- phase 1: logits A[n][m] = rpe[m,b] * dot(keys[m,b,:], q[n,:]) ---
    {
        const float4 q0 = ((const float4*)sQ)[lane];
        const float4 q1 = ((const float4*)sQ)[32 + lane];
        const float4 q2 = ((const float4*)sQ)[64 + lane];
        const float4 q3 = ((const float4*)sQ)[96 + lane];
        for (int m = warp; m < M; m += 8) {
            const float4 k4 = ((const float4*)(keys + ((size_t)m * BSZ + b) * DKDIM))[lane];
            float p0 = k4.x*q0.x + k4.y*q0.y + k4.z*q0.z + k4.w*q0.w;
            float p1 = k4.x*q1.x + k4.y*q1.y + k4.z*q1.z + k4.w*q1.w;
            float p2 = k4.x*q2.x + k4.y*q2.y + k4.z*q2.z + k4.w*q2.w;
            float p3 = k4.x*q3.x + k4.y*q3.y + k4.z*q3.z + k4.w*q3.w;
            #pragma unroll
            for (int off = 16; off > 0; off >>= 1) {
                p0 += __shfl_down_sync(0xffffffffu, p0, off);
                p1 += __shfl_down_sync(0xffffffffu, p1, off);
                p2 += __shfl_down_sync(0xffffffffu, p2, off);
                p3 += __shfl_down_sync(0xffffffffu, p3, off);
            }
            if (lane == 0) {
                const float r = rpe[(size_t)m * BSZ + b];
                sA[0][m] = p0 * r;
                sA[1][m] = p1 * r;
                sA[2][m] = p2 * r;
                sA[3][m] = p3 * r;
            }
        }
    }
    __syncthreads();

    // --- phase 2: softmax over m, one warp per head ---
    if (warp < NHEAD) {
        float* a = sA[warp];
        float mx = -1e30f;
        for (int m = lane; m < M; m += 32) mx = fmaxf(mx, a[m]);
        #pragma unroll
        for (int off = 16; off > 0; off >>= 1)
            mx = fmaxf(mx, __shfl_xor_sync(0xffffffffu, mx, off));
        float s = 0.0f;
        for (int m = lane; m < M; m += 32) {
            float e = __expf(a[m] - mx);
            a[m] = e;
            s += e;
        }
        #pragma unroll
        for (int off = 16; off > 0; off >>= 1)
            s += __shfl_xor_sync(0xffffffffu, s, off);
        const float inv = 1.0f / s;
        for (int m = lane; m < M; m += 32) a[m] *= inv;
    }
    __syncthreads();

    // --- phase 3: res[n][2t..2t+1] = sum_m w[n][m] * vals[m,b,2t..2t+1] ---
    float acc[NHEAD][2] = {};
    const float2* __restrict__ V2 = (const float2*)vals;
    const size_t rowstride = (size_t)BSZ * (VDIM / 2);   // float2 units per m step
    const size_t base = (size_t)b * (VDIM / 2) + tid;

    const int M4 = M & ~3;
    for (int m0 = 0; m0 < M4; m0 += 4) {
        // batch the 4 global loads for MLP
        const float2 va0 = V2[base + (size_t)(m0 + 0) * rowstride];
        const float2 va1 = V2[base + (size_t)(m0 + 1) * rowstride];
        const float2 va2 = V2[base + (size_t)(m0 + 2) * rowstride];
        const float2 va3 = V2[base + (size_t)(m0 + 3) * rowstride];
        const float4 w0 = *(const float4*)&sA[0][m0];
        const float4 w1 = *(const float4*)&sA[1][m0];
        const float4 w2 = *(const float4*)&sA[2][m0];
        const float4 w3 = *(const float4*)&sA[3][m0];

        acc[0][0] += w0.x*va0.x; acc[0][1] += w0.x*va0.y;
        acc[1][0] += w1.x*va0.x; acc[1][1] += w1.x*va0.y;
        acc[2][0] += w2.x*va0.x; acc[2][1] += w2.x*va0.y;
        acc[3][0] += w3.x*va0.x; acc[3][1] += w3.x*va0.y;

        acc[0][0] += w0.y*va1.x; acc[0][1] += w0.y*va1.y;
        acc[1][0] += w1.y*va1.x; acc[1][1] += w1.y*va1.y;
        acc[2][0] += w2.y*va1.x; acc[2][1] += w2.y*va1.y;
        acc[3][0] += w3.y*va1.x; acc[3][1] += w3.y*va1.y;

        acc[0][0] += w0.z*va2.x; acc[0][1] += w0.z*va2.y;
        acc[1][0] += w1.z*va2.x; acc[1][1] += w1.z*va2.y;
        acc[2][0] += w2.z*va2.x; acc[2][1] += w2.z*va2.y;
        acc[3][0] += w3.z*va2.x; acc[3][1] += w3.z*va2.y;

        acc[0][0] += w0.w*va3.x; acc[0][1] += w0.w*va3.y;
        acc[1][0] += w1.w*va3.x; acc[1][1] += w1.w*va3.y;
        acc[2][0] += w2.w*va3.x; acc[2][1] += w2.w*va3.y;
        acc[3][0] += w3.w*va3.x; acc[3][1] += w3.w*va3.y;
    }
    for (int m = M4; m < M; ++m) {
        const float2 v = V2[base + (size_t)m * rowstride];
        #pragma unroll
        for (int n = 0; n < NHEAD; ++n) {
            const float w = sA[n][m];
            acc[n][0] += w * v.x;
            acc[n][1] += w * v.y;
        }
    }

    // --- write res scratch: res_flat[b][n*VDIM + v] ---
    const int v0 = 2 * tid;
    #pragma unroll
    for (int n = 0; n < NHEAD; ++n) {
        float2 o; o.x = acc[n][0]; o.y = acc[n][1];
        *(float2*)&g_res[((size_t)b * NHEAD + n) * VDIM + v0] = o;
    }
}

// ---------------------------------------------------------------------------
// Kernel B: out[1024][512] = res[1024][2048] @ W[512][2048]^T + bias
// 64x64 tiles, BK=16, 256 threads, 4x4 per thread.
// ---------------------------------------------------------------------------
#define BM 64
#define BN 64
#define BK 16

__global__ __launch_bounds__(256) void dnd_gemm_kernel(
    const float* __restrict__ Wt,    // [OUTD][KIN]
    const float* __restrict__ bias,  // [OUTD]
    float* __restrict__ out)         // [BSZ][OUTD]
{
    __shared__ __align__(16) float As[BK][BM];
    __shared__ __align__(16) float Bs[BK][BN];

    const int bx = blockIdx.x;   // N tile (0..7)
    const int by = blockIdx.y;   // M tile (0..15)
    const int tid = threadIdx.x;
    const int tx = tid & 15;     // N dir
    const int ty = tid >> 4;     // M dir

    const int arow = tid >> 2;          // 0..63
    const int acol = (tid & 3) * 4;     // 0,4,8,12

    const float* __restrict__ A = g_res;

    float acc[4][4] = {};

    const float* aptr = A  + ((size_t)(by * BM + arow)) * KIN + acol;
    const float* bptr = Wt + ((size_t)(bx * BN + arow)) * KIN + acol;

    for (int k0 = 0; k0 < KIN; k0 += BK) {
        const float4 a4 = *(const float4*)(aptr + k0);
        const float4 b4 = *(const float4*)(bptr + k0);
        As[acol + 0][arow] = a4.x;
        As[acol + 1][arow] = a4.y;
        As[acol + 2][arow] = a4.z;
        As[acol + 3][arow] = a4.w;
        Bs[acol + 0][arow] = b4.x;
        Bs[acol + 1][arow] = b4.y;
        Bs[acol + 2][arow] = b4.z;
        Bs[acol + 3][arow] = b4.w;
        __syncthreads();

        #pragma unroll
        for (int k = 0; k < BK; ++k) {
            const float4 av = *(const float4*)&As[k][ty * 4];
            const float4 bv = *(const float4*)&Bs[k][tx * 4];
            acc[0][0] += av.x * bv.x; acc[0][1] += av.x * bv.y;
            acc[0][2] += av.x * bv.z; acc[0][3] += av.x * bv.w;
            acc[1][0] += av.y * bv.x; acc[1][1] += av.y * bv.y;
            acc[1][2] += av.y * bv.z; acc[1][3] += av.y * bv.w;
            acc[2][0] += av.z * bv.x; acc[2][1] += av.z * bv.y;
            acc[2][2] += av.z * bv.z; acc[2][3] += av.z * bv.w;
            acc[3][0] += av.w * bv.x; acc[3][1] += av.w * bv.y;
            acc[3][2] += av.w * bv.z; acc[3][3] += av.w * bv.w;
        }
        __syncthreads();
    }

    const int orow = by * BM + ty * 4;
    const int ocol = bx * BN + tx * 4;
    const float4 bz = *(const float4*)(bias + ocol);
    #pragma unroll
    for (int i = 0; i < 4; ++i) {
        float4 o;
        o.x = acc[i][0] + bz.x;
        o.y = acc[i][1] + bz.y;
        o.z = acc[i][2] + bz.z;
        o.w = acc[i][3] + bz.w;
        *(float4*)(out + (size_t)(orow + i) * OUTD + ocol) = o;
    }
}

// ---------------------------------------------------------------------------
// Launch
// ---------------------------------------------------------------------------
extern "C" void kernel_launch(void* const* d_in, const int* in_sizes, int n_in,
                              void* d_out, int out_size)
{
    const float* keys  = (const float*)d_in[0];   // [T][B][DK]
    const float* vals  = (const float*)d_in[1];   // [T][B][2H]
    const float* rpe   = (const float*)d_in[2];   // [T][B][1]
    const float* query = (const float*)d_in[3];   // [B][NH][DK]
    const float* W     = (const float*)d_in[4];   // [2H][NH*2H]
    const float* bias  = (const float*)d_in[5];   // [2H]
    const int*   mstep = (const int*)d_in[6];     // scalar

    float* out = (float*)d_out;                   // [B][2H]

    dnd_attn_kernel<<<BSZ, 256>>>(keys, vals, rpe, query, mstep);

    dim3 ggrid(OUTD / BN, BSZ / BM);              // (8, 16)
    dnd_gemm_kernel<<<ggrid, 256>>>(W, bias, out);
}

// round 4
// speedup vs baseline: 1.1471x; 1.1471x over previous
#include <cuda_runtime.h>
#include <cstdint>

// Problem constants: T=512, B=1024, DK=128, H=256, NH=4
#define T_MAX 512
#define BSZ   1024
#define DKDIM 128
#define VDIM  512      // 2*H
#define NHEAD 4
#define OUTD  512      // 2*H
#define KIN   2048     // NH*2*H

// scratch: res [B][KIN] (8MB) + GEMM split-K partials [2][B][OUTD] (4MB)
__device__ float g_res[(size_t)BSZ * KIN];
__device__ float g_part[(size_t)2 * BSZ * OUTD];

// ---------------------------------------------------------------------------
// Kernel A: fused (keys*rpe) @ q^T -> softmax over slots -> weighted sum of vals
// One CTA per batch element b. 256 threads.
// ---------------------------------------------------------------------------
__global__ __launch_bounds__(256) void dnd_attn_kernel(
    const float* __restrict__ keys,   // [T][B][DK]
    const float* __restrict__ vals,   // [T][B][VDIM]
    const float* __restrict__ rpe,    // [T][B]
    const float* __restrict__ query,  // [B][NH][DK]
    const int*   __restrict__ min_step_p)
{
    __shared__ __align__(16) float sQ[NHEAD * DKDIM];     // 2 KB
    __shared__ __align__(16) float sA[NHEAD][T_MAX];      // 8 KB, head-major

    const int b    = blockIdx.x;
    const int tid  = threadIdx.x;
    const int warp = tid >> 5;
    const int lane = tid & 31;
    const int M    = min_step_p[0];

    // --- load query heads to smem ---
    for (int i = tid; i < NHEAD * DKDIM; i += 256)
        sQ[i] = query[(size_t)b * NHEAD * DKDIM + i];
    __syncthreads();

    // --- phase 1: logits A[n][m] = rpe[m,b] * dot(keys[m,b,:], q[n,:]) ---
    // 8 lanes per head: lane = h*8 + j. Each lane covers 16 of 128 dk elems,
    // reduce over 8 lanes -> only 3 shuffles per slot.
    {
        const int h = lane >> 3;
        const int j = lane & 7;
        float4 q4[4];
        #pragma unroll
        for (int it = 0; it < 4; ++it)
            q4[it] = ((const float4*)sQ)[h * 32 + it * 8 + j];

        for (int m = warp; m < M; m += 8) {
            const float4* __restrict__ krow =
                (const float4*)(keys + ((size_t)m * BSZ + b) * DKDIM);
            float p = 0.0f;
            #pragma unroll
            for (int it = 0; it < 4; ++it) {
                const float4 k4 = krow[it * 8 + j];
                p += k4.x * q4[it].x + k4.y * q4[it].y
                   + k4.z * q4[it].z + k4.w * q4[it].w;
            }
            p += __shfl_down_sync(0xffffffffu, p, 4);
            p += __shfl_down_sync(0xffffffffu, p, 2);
            p += __shfl_down_sync(0xffffffffu, p, 1);
            if (j == 0)
                sA[h][m] = p * __ldg(&rpe[(size_t)m * BSZ + b]);
        }
    }
    __syncthreads();

    // --- phase 2: softmax over m, one warp per head ---
    if (warp < NHEAD) {
        float* a = sA[warp];
        float mx = -1e30f;
        for (int m = lane; m < M; m += 32) mx = fmaxf(mx, a[m]);
        #pragma unroll
        for (int off = 16; off > 0; off >>= 1)
            mx = fmaxf(mx, __shfl_xor_sync(0xffffffffu, mx, off));
        float s = 0.0f;
        for (int m = lane; m < M; m += 32) {
            float e = __expf(a[m] - mx);
            a[m] = e;
            s += e;
        }
        #pragma unroll
        for (int off = 16; off > 0; off >>= 1)
            s += __shfl_xor_sync(0xffffffffu, s, off);
        const float inv = 1.0f / s;
        for (int m = lane; m < M; m += 32) a[m] *= inv;
    }
    __syncthreads();

    // --- phase 3: res[n][2t..2t+1] = sum_m w[n][m] * vals[m,b,2t..2t+1] ---
    float acc[NHEAD][2] = {};
    const float2* __restrict__ V2 = (const float2*)vals;
    const size_t rowstride = (size_t)BSZ * (VDIM / 2);   // float2 units per m step
    const size_t base = (size_t)b * (VDIM / 2) + tid;

    const int M4 = M & ~3;
    for (int m0 = 0; m0 < M4; m0 += 4) {
        const float2 va0 = V2[base + (size_t)(m0 + 0) * rowstride];
        const float2 va1 = V2[base + (size_t)(m0 + 1) * rowstride];
        const float2 va2 = V2[base + (size_t)(m0 + 2) * rowstride];
        const float2 va3 = V2[base + (size_t)(m0 + 3) * rowstride];
        const float4 w0 = *(const float4*)&sA[0][m0];
        const float4 w1 = *(const float4*)&sA[1][m0];
        const float4 w2 = *(const float4*)&sA[2][m0];
        const float4 w3 = *(const float4*)&sA[3][m0];

        acc[0][0] += w0.x*va0.x; acc[0][1] += w0.x*va0.y;
        acc[1][0] += w1.x*va0.x; acc[1][1] += w1.x*va0.y;
        acc[2][0] += w2.x*va0.x; acc[2][1] += w2.x*va0.y;
        acc[3][0] += w3.x*va0.x; acc[3][1] += w3.x*va0.y;

        acc[0][0] += w0.y*va1.x; acc[0][1] += w0.y*va1.y;
        acc[1][0] += w1.y*va1.x; acc[1][1] += w1.y*va1.y;
        acc[2][0] += w2.y*va1.x; acc[2][1] += w2.y*va1.y;
        acc[3][0] += w3.y*va1.x; acc[3][1] += w3.y*va1.y;

        acc[0][0] += w0.z*va2.x; acc[0][1] += w0.z*va2.y;
        acc[1][0] += w1.z*va2.x; acc[1][1] += w1.z*va2.y;
        acc[2][0] += w2.z*va2.x; acc[2][1] += w2.z*va2.y;
        acc[3][0] += w3.z*va2.x; acc[3][1] += w3.z*va2.y;

        acc[0][0] += w0.w*va3.x; acc[0][1] += w0.w*va3.y;
        acc[1][0] += w1.w*va3.x; acc[1][1] += w1.w*va3.y;
        acc[2][0] += w2.w*va3.x; acc[2][1] += w2.w*va3.y;
        acc[3][0] += w3.w*va3.x; acc[3][1] += w3.w*va3.y;
    }
    for (int m = M4; m < M; ++m) {
        const float2 v = V2[base + (size_t)m * rowstride];
        #pragma unroll
        for (int n = 0; n < NHEAD; ++n) {
            const float w = sA[n][m];
            acc[n][0] += w * v.x;
            acc[n][1] += w * v.y;
        }
    }

    const int v0 = 2 * tid;
    #pragma unroll
    for (int n = 0; n < NHEAD; ++n) {
        float2 o; o.x = acc[n][0]; o.y = acc[n][1];
        *(float2*)&g_res[((size_t)b * NHEAD + n) * VDIM + v0] = o;
    }
}

// ---------------------------------------------------------------------------
// Kernel B: split-K GEMM. part[kz] = res[.,kz-half] @ W[.,kz-half]^T
// 64x64 tile, BK=16, 256 threads, 4x4 per thread, double-buffered smem.
// grid (8, 16, 2) = 256 CTAs.
// Smem rows padded by +4 floats: stride 68*4=272 B (16B multiple) keeps
// LDS.128 alignment while skewing banks.
// ---------------------------------------------------------------------------
#define GBM 64
#define GBN 64
#define GBK 16
#define GPAD 4
#define KSPLIT 2
#define KHALF (KIN / KSPLIT)   // 1024

__global__ __launch_bounds__(256) void dnd_gemm_kernel(
    const float* __restrict__ Wt)    // [OUTD][KIN]
{
    __shared__ __align__(16) float As[2][GBK][GBM + GPAD];
    __shared__ __align__(16) float Bs[2][GBK][GBN + GPAD];

    const int bx = blockIdx.x;   // N tile (0..7)
    const int by = blockIdx.y;   // M tile (0..15)
    const int kz = blockIdx.z;   // K split (0..1)
    const int tid = threadIdx.x;
    const int tx = tid & 15;     // N dir
    const int ty = tid >> 4;     // M dir

    const int arow = tid >> 2;          // 0..63
    const int acol = (tid & 3) * 4;     // 0,4,8,12

    const float* __restrict__ aptr =
        g_res + ((size_t)(by * GBM + arow)) * KIN + kz * KHALF + acol;
    const float* __restrict__ bptr =
        Wt    + ((size_t)(bx * GBN + arow)) * KIN + kz * KHALF + acol;

    float4 fa = *(const float4*)aptr;
    float4 fb = *(const float4*)bptr;

    As[0][acol + 0][arow] = fa.x;
    As[0][acol + 1][arow] = fa.y;
    As[0][acol + 2][arow] = fa.z;
    As[0][acol + 3][arow] = fa.w;
    Bs[0][acol + 0][arow] = fb.x;
    Bs[0][acol + 1][arow] = fb.y;
    Bs[0][acol + 2][arow] = fb.z;
    Bs[0][acol + 3][arow] = fb.w;
    __syncthreads();

    float acc[4][4] = {};
    int buf = 0;

    for (int k0 = GBK; k0 <= KHALF; k0 += GBK) {
        const bool more = (k0 < KHALF);
        if (more) {
            fa = *(const float4*)(aptr + k0);
            fb = *(const float4*)(bptr + k0);
        }

        #pragma unroll
        for (int k = 0; k < GBK; ++k) {
            const float4 av = *(const float4*)&As[buf][k][ty * 4];
            const float4 bv = *(const float4*)&Bs[buf][k][tx * 4];
            acc[0][0] += av.x * bv.x; acc[0][1] += av.x * bv.y;
            acc[0][2] += av.x * bv.z; acc[0][3] += av.x * bv.w;
            acc[1][0] += av.y * bv.x; acc[1][1] += av.y * bv.y;
            acc[1][2] += av.y * bv.z; acc[1][3] += av.y * bv.w;
            acc[2][0] += av.z * bv.x; acc[2][1] += av.z * bv.y;
            acc[2][2] += av.z * bv.z; acc[2][3] += av.z * bv.w;
            acc[3][0] += av.w * bv.x; acc[3][1] += av.w * bv.y;
            acc[3][2] += av.w * bv.z; acc[3][3] += av.w * bv.w;
        }

        if (more) {
            const int nb = buf ^ 1;
            As[nb][acol + 0][arow] = fa.x;
            As[nb][acol + 1][arow] = fa.y;
            As[nb][acol + 2][arow] = fa.z;
            As[nb][acol + 3][arow] = fa.w;
            Bs[nb][acol + 0][arow] = fb.x;
            Bs[nb][acol + 1][arow] = fb.y;
            Bs[nb][acol + 2][arow] = fb.z;
            Bs[nb][acol + 3][arow] = fb.w;
        }
        __syncthreads();
        buf ^= 1;
    }

    float* __restrict__ part = g_part + (size_t)kz * BSZ * OUTD;
    const int orow = by * GBM + ty * 4;
    const int ocol = bx * GBN + tx * 4;
    #pragma unroll
    for (int i = 0; i < 4; ++i) {
        float4 o;
        o.x = acc[i][0]; o.y = acc[i][1]; o.z = acc[i][2]; o.w = acc[i][3];
        *(float4*)(part + (size_t)(orow + i) * OUTD + ocol) = o;
    }
}

// ---------------------------------------------------------------------------
// Kernel C: out = part0 + part1 + bias  (vectorized float4)
// ---------------------------------------------------------------------------
__global__ __launch_bounds__(256) void dnd_reduce_kernel(
    const float* __restrict__ bias,
    float* __restrict__ out)
{
    const int i = blockIdx.x * 256 + threadIdx.x;   // float4 index
    const float4 a = ((const float4*)g_part)[i];
    const float4 c = ((const float4*)(g_part + (size_t)BSZ * OUTD))[i];
    const float4 bz = ((const float4*)bias)[i & (OUTD / 4 - 1)];
    float4 o;
    o.x = a.x + c.x + bz.x;
    o.y = a.y + c.y + bz.y;
    o.z = a.z + c.z + bz.z;
    o.w = a.w + c.w + bz.w;
    ((float4*)out)[i] = o;
}

// ---------------------------------------------------------------------------
// Launch
// ---------------------------------------------------------------------------
extern "C" void kernel_launch(void* const* d_in, const int* in_sizes, int n_in,
                              void* d_out, int out_size)
{
    const float* keys  = (const float*)d_in[0];   // [T][B][DK]
    const float* vals  = (const float*)d_in[1];   // [T][B][2H]
    const float* rpe   = (const float*)d_in[2];   // [T][B][1]
    const float* query = (const float*)d_in[3];   // [B][NH][DK]
    const float* W     = (const float*)d_in[4];   // [2H][NH*2H]
    const float* bias  = (const float*)d_in[5];   // [2H]
    const int*   mstep = (const int*)d_in[6];     // scalar

    float* out = (float*)d_out;                   // [B][2H]

    dnd_attn_kernel<<<BSZ, 256>>>(keys, vals, rpe, query, mstep);

    dim3 ggrid(OUTD / GBN, BSZ / GBM, KSPLIT);    // (8, 16, 2)
    dnd_gemm_kernel<<<ggrid, 256>>>(W);

    dnd_reduce_kernel<<<(BSZ * OUTD / 4) / 256, 256>>>(bias, out);
}

// round 5
// speedup vs baseline: 1.2857x; 1.1208x over previous
#include <cuda_runtime.h>
#include <cstdint>

// Problem constants: T=512, B=1024, DK=128, H=256, NH=4
#define T_MAX 512
#define BSZ   1024
#define DKDIM 128
#define VDIM  512      // 2*H
#define NHEAD 4
#define OUTD  512      // 2*H
#define KIN   2048     // NH*2*H

// scratch: weights [B][NH][T] (8MB), res [B][KIN] (8MB), split-K partials (4MB)
__device__ float g_w[(size_t)BSZ * NHEAD * T_MAX];
__device__ float g_res[(size_t)BSZ * KIN];
__device__ float g_part[(size_t)2 * BSZ * OUTD];

// ---------------------------------------------------------------------------
// Kernel A1: logits + softmax -> normalized weights g_w[b][n][m]
// One CTA per batch element. 256 threads.
// ---------------------------------------------------------------------------
__global__ __launch_bounds__(256) void dnd_weights_kernel(
    const float* __restrict__ keys,   // [T][B][DK]
    const float* __restrict__ rpe,    // [T][B]
    const float* __restrict__ query,  // [B][NH][DK]
    const int*   __restrict__ min_step_p)
{
    __shared__ __align__(16) float sQ[NHEAD * DKDIM];     // 2 KB
    __shared__ __align__(16) float sA[NHEAD][T_MAX];      // 8 KB

    const int b    = blockIdx.x;
    const int tid  = threadIdx.x;
    const int warp = tid >> 5;
    const int lane = tid & 31;
    const int M    = min_step_p[0];

    for (int i = tid; i < NHEAD * DKDIM; i += 256)
        sQ[i] = query[(size_t)b * NHEAD * DKDIM + i];
    __syncthreads();

    // phase 1: 8 lanes per head (lane = h*8+j); each warp does 2 slots per
    // iteration so 8 independent 16B key loads are in flight.
    {
        const int h = lane >> 3;
        const int j = lane & 7;
        float4 q4[4];
        #pragma unroll
        for (int it = 0; it < 4; ++it)
            q4[it] = ((const float4*)sQ)[h * 32 + it * 8 + j];

        const int Mfull = M & ~15;   // pairs of slots per warp stride 16
        for (int m = warp; m < Mfull; m += 16) {
            const int m1 = m + 8;
            const float4* __restrict__ ka =
                (const float4*)(keys + ((size_t)m  * BSZ + b) * DKDIM);
            const float4* __restrict__ kb =
                (const float4*)(keys + ((size_t)m1 * BSZ + b) * DKDIM);
            float4 la[4], lb[4];
            #pragma unroll
            for (int it = 0; it < 4; ++it) { la[it] = ka[it * 8 + j]; }
            #pragma unroll
            for (int it = 0; it < 4; ++it) { lb[it] = kb[it * 8 + j]; }
            float pa = 0.0f, pb = 0.0f;
            #pragma unroll
            for (int it = 0; it < 4; ++it) {
                pa += la[it].x * q4[it].x + la[it].y * q4[it].y
                    + la[it].z * q4[it].z + la[it].w * q4[it].w;
                pb += lb[it].x * q4[it].x + lb[it].y * q4[it].y
                    + lb[it].z * q4[it].z + lb[it].w * q4[it].w;
            }
            pa += __shfl_down_sync(0xffffffffu, pa, 4);
            pb += __shfl_down_sync(0xffffffffu, pb, 4);
            pa += __shfl_down_sync(0xffffffffu, pa, 2);
            pb += __shfl_down_sync(0xffffffffu, pb, 2);
            pa += __shfl_down_sync(0xffffffffu, pa, 1);
            pb += __shfl_down_sync(0xffffffffu, pb, 1);
            if (j == 0) {
                sA[h][m]  = pa * __ldg(&rpe[(size_t)m  * BSZ + b]);
                sA[h][m1] = pb * __ldg(&rpe[(size_t)m1 * BSZ + b]);
            }
        }
        for (int m = Mfull + warp; m < M; m += 8) {
            const float4* __restrict__ krow =
                (const float4*)(keys + ((size_t)m * BSZ + b) * DKDIM);
            float p = 0.0f;
            #pragma unroll
            for (int it = 0; it < 4; ++it) {
                const float4 k4 = krow[it * 8 + j];
                p += k4.x * q4[it].x + k4.y * q4[it].y
                   + k4.z * q4[it].z + k4.w * q4[it].w;
            }
            p += __shfl_down_sync(0xffffffffu, p, 4);
            p += __shfl_down_sync(0xffffffffu, p, 2);
            p += __shfl_down_sync(0xffffffffu, p, 1);
            if (j == 0)
                sA[h][m] = p * __ldg(&rpe[(size_t)m * BSZ + b]);
        }
    }
    __syncthreads();

    // phase 2: softmax per head (one warp per head)
    if (warp < NHEAD) {
        float* a = sA[warp];
        float mx = -1e30f;
        for (int m = lane; m < M; m += 32) mx = fmaxf(mx, a[m]);
        #pragma unroll
        for (int off = 16; off > 0; off >>= 1)
            mx = fmaxf(mx, __shfl_xor_sync(0xffffffffu, mx, off));
        float s = 0.0f;
        for (int m = lane; m < M; m += 32) {
            float e = __expf(a[m] - mx);
            a[m] = e;
            s += e;
        }
        #pragma unroll
        for (int off = 16; off > 0; off >>= 1)
            s += __shfl_xor_sync(0xffffffffu, s, off);
        const float inv = 1.0f / s;
        for (int m = lane; m < M; m += 32) a[m] *= inv;
    }
    __syncthreads();

    // write weights (whole 2048-float block; beyond-M entries unused by A2)
    {
        const float4* sA4 = (const float4*)&sA[0][0];
        float4* w4 = (float4*)(g_w + (size_t)b * NHEAD * T_MAX);
        #pragma unroll
        for (int i = 0; i < 2; ++i)
            w4[tid + 256 * i] = sA4[tid + 256 * i];
    }
}

// ---------------------------------------------------------------------------
// Kernel A2: res[b][n][v] = sum_m w[b][n][m] * vals[m][b][v]
// grid (2, BSZ): 2 v-chunks of 256 floats. 128 threads, 8-slot unroll.
// ---------------------------------------------------------------------------
__global__ __launch_bounds__(128) void dnd_apply_kernel(
    const float* __restrict__ vals,   // [T][B][VDIM]
    const int*   __restrict__ min_step_p)
{
    __shared__ __align__(16) float sW[NHEAD][T_MAX];   // 8 KB

    const int chunk = blockIdx.x;     // 0..1
    const int b     = blockIdx.y;
    const int tid   = threadIdx.x;    // 0..127
    const int M     = min_step_p[0];

    // stage weights
    {
        const float4* w4 = (const float4*)(g_w + (size_t)b * NHEAD * T_MAX);
        float4* s4 = (float4*)&sW[0][0];
        #pragma unroll
        for (int i = 0; i < 4; ++i)
            s4[tid + 128 * i] = w4[tid + 128 * i];
    }
    __syncthreads();

    float acc[NHEAD][2] = {};
    const float2* __restrict__ V2 = (const float2*)vals;
    const size_t rowstride = (size_t)BSZ * (VDIM / 2);
    const size_t base = (size_t)b * (VDIM / 2) + chunk * 128 + tid;

    const int M8 = M & ~7;
    for (int m0 = 0; m0 < M8; m0 += 8) {
        float2 v[8];
        #pragma unroll
        for (int u = 0; u < 8; ++u)
            v[u] = V2[base + (size_t)(m0 + u) * rowstride];

        #pragma unroll
        for (int n = 0; n < NHEAD; ++n) {
            const float4 wa = *(const float4*)&sW[n][m0];
            const float4 wb = *(const float4*)&sW[n][m0 + 4];
            acc[n][0] += wa.x * v[0].x; acc[n][1] += wa.x * v[0].y;
            acc[n][0] += wa.y * v[1].x; acc[n][1] += wa.y * v[1].y;
            acc[n][0] += wa.z * v[2].x; acc[n][1] += wa.z * v[2].y;
            acc[n][0] += wa.w * v[3].x; acc[n][1] += wa.w * v[3].y;
            acc[n][0] += wb.x * v[4].x; acc[n][1] += wb.x * v[4].y;
            acc[n][0] += wb.y * v[5].x; acc[n][1] += wb.y * v[5].y;
            acc[n][0] += wb.z * v[6].x; acc[n][1] += wb.z * v[6].y;
            acc[n][0] += wb.w * v[7].x; acc[n][1] += wb.w * v[7].y;
        }
    }
    for (int m = M8; m < M; ++m) {
        const float2 v = V2[base + (size_t)m * rowstride];
        #pragma unroll
        for (int n = 0; n < NHEAD; ++n) {
            const float w = sW[n][m];
            acc[n][0] += w * v.x;
            acc[n][1] += w * v.y;
        }
    }

    const int v0 = chunk * 256 + 2 * tid;
    #pragma unroll
    for (int n = 0; n < NHEAD; ++n) {
        float2 o; o.x = acc[n][0]; o.y = acc[n][1];
        *(float2*)&g_res[((size_t)b * NHEAD + n) * VDIM + v0] = o;
    }
}

// ---------------------------------------------------------------------------
// Kernel B: split-K GEMM. part[kz] = res[.,half kz] @ W[.,half kz]^T
// 64x64 tile, BK=16, 256 threads, 4x4/thread, double-buffered. grid (8,16,2).
// ---------------------------------------------------------------------------
#define GBM 64
#define GBN 64
#define GBK 16
#define GPAD 4
#define KSPLIT 2
#define KHALF (KIN / KSPLIT)   // 1024

__global__ __launch_bounds__(256) void dnd_gemm_kernel(
    const float* __restrict__ Wt)    // [OUTD][KIN]
{
    __shared__ __align__(16) float As[2][GBK][GBM + GPAD];
    __shared__ __align__(16) float Bs[2][GBK][GBN + GPAD];

    const int bx = blockIdx.x;
    const int by = blockIdx.y;
    const int kz = blockIdx.z;
    const int tid = threadIdx.x;
    const int tx = tid & 15;
    const int ty = tid >> 4;

    const int arow = tid >> 2;
    const int acol = (tid & 3) * 4;

    const float* __restrict__ aptr =
        g_res + ((size_t)(by * GBM + arow)) * KIN + kz * KHALF + acol;
    const float* __restrict__ bptr =
        Wt    + ((size_t)(bx * GBN + arow)) * KIN + kz * KHALF + acol;

    float4 fa = *(const float4*)aptr;
    float4 fb = *(const float4*)bptr;

    As[0][acol + 0][arow] = fa.x;
    As[0][acol + 1][arow] = fa.y;
    As[0][acol + 2][arow] = fa.z;
    As[0][acol + 3][arow] = fa.w;
    Bs[0][acol + 0][arow] = fb.x;
    Bs[0][acol + 1][arow] = fb.y;
    Bs[0][acol + 2][arow] = fb.z;
    Bs[0][acol + 3][arow] = fb.w;
    __syncthreads();

    float acc[4][4] = {};
    int buf = 0;

    for (int k0 = GBK; k0 <= KHALF; k0 += GBK) {
        const bool more = (k0 < KHALF);
        if (more) {
            fa = *(const float4*)(aptr + k0);
            fb = *(const float4*)(bptr + k0);
        }

        #pragma unroll
        for (int k = 0; k < GBK; ++k) {
            const float4 av = *(const float4*)&As[buf][k][ty * 4];
            const float4 bv = *(const float4*)&Bs[buf][k][tx * 4];
            acc[0][0] += av.x * bv.x; acc[0][1] += av.x * bv.y;
            acc[0][2] += av.x * bv.z; acc[0][3] += av.x * bv.w;
            acc[1][0] += av.y * bv.x; acc[1][1] += av.y * bv.y;
            acc[1][2] += av.y * bv.z; acc[1][3] += av.y * bv.w;
            acc[2][0] += av.z * bv.x; acc[2][1] += av.z * bv.y;
            acc[2][2] += av.z * bv.z; acc[2][3] += av.z * bv.w;
            acc[3][0] += av.w * bv.x; acc[3][1] += av.w * bv.y;
            acc[3][2] += av.w * bv.z; acc[3][3] += av.w * bv.w;
        }

        if (more) {
            const int nb = buf ^ 1;
            As[nb][acol + 0][arow] = fa.x;
            As[nb][acol + 1][arow] = fa.y;
            As[nb][acol + 2][arow] = fa.z;
            As[nb][acol + 3][arow] = fa.w;
            Bs[nb][acol + 0][arow] = fb.x;
            Bs[nb][acol + 1][arow] = fb.y;
            Bs[nb][acol + 2][arow] = fb.z;
            Bs[nb][acol + 3][arow] = fb.w;
        }
        __syncthreads();
        buf ^= 1;
    }

    float* __restrict__ part = g_part + (size_t)kz * BSZ * OUTD;
    const int orow = by * GBM + ty * 4;
    const int ocol = bx * GBN + tx * 4;
    #pragma unroll
    for (int i = 0; i < 4; ++i) {
        float4 o;
        o.x = acc[i][0]; o.y = acc[i][1]; o.z = acc[i][2]; o.w = acc[i][3];
        *(float4*)(part + (size_t)(orow + i) * OUTD + ocol) = o;
    }
}

// ---------------------------------------------------------------------------
// Kernel C: out = part0 + part1 + bias
// ---------------------------------------------------------------------------
__global__ __launch_bounds__(256) void dnd_reduce_kernel(
    const float* __restrict__ bias,
    float* __restrict__ out)
{
    const int i = blockIdx.x * 256 + threadIdx.x;
    const float4 a = ((const float4*)g_part)[i];
    const float4 c = ((const float4*)(g_part + (size_t)BSZ * OUTD))[i];
    const float4 bz = ((const float4*)bias)[i & (OUTD / 4 - 1)];
    float4 o;
    o.x = a.x + c.x + bz.x;
    o.y = a.y + c.y + bz.y;
    o.z = a.z + c.z + bz.z;
    o.w = a.w + c.w + bz.w;
    ((float4*)out)[i] = o;
}

// ---------------------------------------------------------------------------
// Launch
// ---------------------------------------------------------------------------
extern "C" void kernel_launch(void* const* d_in, const int* in_sizes, int n_in,
                              void* d_out, int out_size)
{
    const float* keys  = (const float*)d_in[0];
    const float* vals  = (const float*)d_in[1];
    const float* rpe   = (const float*)d_in[2];
    const float* query = (const float*)d_in[3];
    const float* W     = (const float*)d_in[4];
    const float* bias  = (const float*)d_in[5];
    const int*   mstep = (const int*)d_in[6];

    float* out = (float*)d_out;

    dnd_weights_kernel<<<BSZ, 256>>>(keys, rpe, query, mstep);

    dim3 agrid(2, BSZ);
    dnd_apply_kernel<<<agrid, 128>>>(vals, mstep);

    dim3 ggrid(OUTD / GBN, BSZ / GBM, KSPLIT);
    dnd_gemm_kernel<<<ggrid, 256>>>(W);

    dnd_reduce_kernel<<<(BSZ * OUTD / 4) / 256, 256>>>(bias, out);
}

// round 7
// speedup vs baseline: 1.4252x; 1.1086x over previous
#include <cuda_runtime.h>
#include <cstdint>

// Problem constants: T=512, B=1024, DK=128, H=256, NH=4
#define T_MAX 512
#define BSZ   1024
#define DKDIM 128
#define VDIM  512      // 2*H
#define NHEAD 4
#define OUTD  512      // 2*H
#define KIN   2048     // NH*2*H

// scratch: weights [B][NH][T] (8MB), res [B][KIN] (8MB), split-K partials (8MB)
__device__ float g_w[(size_t)BSZ * NHEAD * T_MAX];
__device__ float g_res[(size_t)BSZ * KIN];
__device__ float g_part[(size_t)4 * BSZ * OUTD];

// ---------------------------------------------------------------------------
// Kernel A1: logits + softmax -> normalized weights g_w[b][n][m]
// One CTA per batch element. 256 threads.
// ---------------------------------------------------------------------------
__global__ __launch_bounds__(256) void dnd_weights_kernel(
    const float* __restrict__ keys,   // [T][B][DK]
    const float* __restrict__ rpe,    // [T][B]
    const float* __restrict__ query,  // [B][NH][DK]
    const int*   __restrict__ min_step_p)
{
    __shared__ __align__(16) float sQ[NHEAD * DKDIM];     // 2 KB
    __shared__ __align__(16) float sA[NHEAD][T_MAX];      // 8 KB

    const int b    = blockIdx.x;
    const int tid  = threadIdx.x;
    const int warp = tid >> 5;
    const int lane = tid & 31;
    const int M    = min_step_p[0];

    for (int i = tid; i < NHEAD * DKDIM; i += 256)
        sQ[i] = query[(size_t)b * NHEAD * DKDIM + i];
    __syncthreads();

    // phase 1: 8 lanes per head (lane = h*8+j); 2 slots per warp iteration.
    {
        const int h = lane >> 3;
        const int j = lane & 7;
        float4 q4[4];
        #pragma unroll
        for (int it = 0; it < 4; ++it)
            q4[it] = ((const float4*)sQ)[h * 32 + it * 8 + j];

        const int Mfull = M & ~15;
        for (int m = warp; m < Mfull; m += 16) {
            const int m1 = m + 8;
            const float4* __restrict__ ka =
                (const float4*)(keys + ((size_t)m  * BSZ + b) * DKDIM);
            const float4* __restrict__ kb =
                (const float4*)(keys + ((size_t)m1 * BSZ + b) * DKDIM);
            float4 la[4], lb[4];
            #pragma unroll
            for (int it = 0; it < 4; ++it) { la[it] = ka[it * 8 + j]; }
            #pragma unroll
            for (int it = 0; it < 4; ++it) { lb[it] = kb[it * 8 + j]; }
            float pa = 0.0f, pb = 0.0f;
            #pragma unroll
            for (int it = 0; it < 4; ++it) {
                pa += la[it].x * q4[it].x + la[it].y * q4[it].y
                    + la[it].z * q4[it].z + la[it].w * q4[it].w;
                pb += lb[it].x * q4[it].x + lb[it].y * q4[it].y
                    + lb[it].z * q4[it].z + lb[it].w * q4[it].w;
            }
            pa += __shfl_down_sync(0xffffffffu, pa, 4);
            pb += __shfl_down_sync(0xffffffffu, pb, 4);
            pa += __shfl_down_sync(0xffffffffu, pa, 2);
            pb += __shfl_down_sync(0xffffffffu, pb, 2);
            pa += __shfl_down_sync(0xffffffffu, pa, 1);
            pb += __shfl_down_sync(0xffffffffu, pb, 1);
            if (j == 0) {
                sA[h][m]  = pa * __ldg(&rpe[(size_t)m  * BSZ + b]);
                sA[h][m1] = pb * __ldg(&rpe[(size_t)m1 * BSZ + b]);
            }
        }
        for (int m = Mfull + warp; m < M; m += 8) {
            const float4* __restrict__ krow =
                (const float4*)(keys + ((size_t)m * BSZ + b) * DKDIM);
            float p = 0.0f;
            #pragma unroll
            for (int it = 0; it < 4; ++it) {
                const float4 k4 = krow[it * 8 + j];
                p += k4.x * q4[it].x + k4.y * q4[it].y
                   + k4.z * q4[it].z + k4.w * q4[it].w;
            }
            p += __shfl_down_sync(0xffffffffu, p, 4);
            p += __shfl_down_sync(0xffffffffu, p, 2);
            p += __shfl_down_sync(0xffffffffu, p, 1);
            if (j == 0)
                sA[h][m] = p * __ldg(&rpe[(size_t)m * BSZ + b]);
        }
    }
    __syncthreads();

    // phase 2: softmax per head (one warp per head)
    if (warp < NHEAD) {
        float* a = sA[warp];
        float mx = -1e30f;
        for (int m = lane; m < M; m += 32) mx = fmaxf(mx, a[m]);
        #pragma unroll
        for (int off = 16; off > 0; off >>= 1)
            mx = fmaxf(mx, __shfl_xor_sync(0xffffffffu, mx, off));
        float s = 0.0f;
        for (int m = lane; m < M; m += 32) {
            float e = __expf(a[m] - mx);
            a[m] = e;
            s += e;
        }
        #pragma unroll
        for (int off = 16; off > 0; off >>= 1)
            s += __shfl_xor_sync(0xffffffffu, s, off);
        const float inv = 1.0f / s;
        for (int m = lane; m < M; m += 32) a[m] *= inv;
    }
    __syncthreads();

    // write weights
    {
        const float4* sA4 = (const float4*)&sA[0][0];
        float4* w4 = (float4*)(g_w + (size_t)b * NHEAD * T_MAX);
        #pragma unroll
        for (int i = 0; i < 2; ++i)
            w4[tid + 256 * i] = sA4[tid + 256 * i];
    }
}

// ---------------------------------------------------------------------------
// Kernel A2: res[b][n][v] = sum_m w[b][n][m] * vals[m][b][v]
// One CTA per b (grid 1024), 128 threads, each thread owns 4 consecutive v.
// float4 (LDG.128) loads, 8-slot unroll -> 128B in flight per thread.
// ---------------------------------------------------------------------------
__global__ __launch_bounds__(128) void dnd_apply_kernel(
    const float* __restrict__ vals,   // [T][B][VDIM]
    const int*   __restrict__ min_step_p)
{
    __shared__ __align__(16) float sW[NHEAD][T_MAX];   // 8 KB

    const int b   = blockIdx.x;
    const int tid = threadIdx.x;    // 0..127
    const int M   = min_step_p[0];

    // stage weights
    {
        const float4* w4 = (const float4*)(g_w + (size_t)b * NHEAD * T_MAX);
        float4* s4 = (float4*)&sW[0][0];
        #pragma unroll
        for (int i = 0; i < 4; ++i)
            s4[tid + 128 * i] = w4[tid + 128 * i];
    }
    __syncthreads();

    float acc[NHEAD][4] = {};
    const float4* __restrict__ V4 = (const float4*)vals;
    const size_t rowstride = (size_t)BSZ * (VDIM / 4);   // float4 units per m
    const size_t base = (size_t)b * (VDIM / 4) + tid;

    const int M8 = M & ~7;
    for (int m0 = 0; m0 < M8; m0 += 8) {
        float4 v[8];
        #pragma unroll
        for (int u = 0; u < 8; ++u)
            v[u] = V4[base + (size_t)(m0 + u) * rowstride];

        #pragma unroll
        for (int n = 0; n < NHEAD; ++n) {
            const float4 wa = *(const float4*)&sW[n][m0];
            const float4 wb = *(const float4*)&sW[n][m0 + 4];
            acc[n][0] += wa.x * v[0].x; acc[n][1] += wa.x * v[0].y;
            acc[n][2] += wa.x * v[0].z; acc[n][3] += wa.x * v[0].w;
            acc[n][0] += wa.y * v[1].x; acc[n][1] += wa.y * v[1].y;
            acc[n][2] += wa.y * v[1].z; acc[n][3] += wa.y * v[1].w;
            acc[n][0] += wa.z * v[2].x; acc[n][1] += wa.z * v[2].y;
            acc[n][2] += wa.z * v[2].z; acc[n][3] += wa.z * v[2].w;
            acc[n][0] += wa.w * v[3].x; acc[n][1] += wa.w * v[3].y;
            acc[n][2] += wa.w * v[3].z; acc[n][3] += wa.w * v[3].w;
            acc[n][0] += wb.x * v[4].x; acc[n][1] += wb.x * v[4].y;
            acc[n][2] += wb.x * v[4].z; acc[n][3] += wb.x * v[4].w;
            acc[n][0] += wb.y * v[5].x; acc[n][1] += wb.y * v[5].y;
            acc[n][2] += wb.y * v[5].z; acc[n][3] += wb.y * v[5].w;
            acc[n][0] += wb.z * v[6].x; acc[n][1] += wb.z * v[6].y;
            acc[n][2] += wb.z * v[6].z; acc[n][3] += wb.z * v[6].w;
            acc[n][0] += wb.w * v[7].x; acc[n][1] += wb.w * v[7].y;
            acc[n][2] += wb.w * v[7].z; acc[n][3] += wb.w * v[7].w;
        }
    }
    for (int m = M8; m < M; ++m) {
        const float4 v = V4[base + (size_t)m * rowstride];
        #pragma unroll
        for (int n = 0; n < NHEAD; ++n) {
            const float w = sW[n][m];
            acc[n][0] += w * v.x; acc[n][1] += w * v.y;
            acc[n][2] += w * v.z; acc[n][3] += w * v.w;
        }
    }

    const int v0 = 4 * tid;
    #pragma unroll
    for (int n = 0; n < NHEAD; ++n) {
        float4 o;
        o.x = acc[n][0]; o.y = acc[n][1]; o.z = acc[n][2]; o.w = acc[n][3];
        *(float4*)&g_res[((size_t)b * NHEAD + n) * VDIM + v0] = o;
    }
}

// ---------------------------------------------------------------------------
// Kernel B: split-K GEMM (K split 4). part[kz] = res[.,Kq kz] @ W[.,Kq kz]^T
// 64x64 tile, BK=16, 256 threads, 4x4/thread, double-buffered. grid (8,16,4).
// ---------------------------------------------------------------------------
#define GBM 64
#define GBN 64
#define GBK 16
#define GPAD 4
#define KSPLIT 4
#define KQ (KIN / KSPLIT)   // 512

__global__ __launch_bounds__(256) void dnd_gemm_kernel(
    const float* __restrict__ Wt)    // [OUTD][KIN]
{
    __shared__ __align__(16) float As[2][GBK][GBM + GPAD];
    __shared__ __align__(16) float Bs[2][GBK][GBN + GPAD];

    const int bx = blockIdx.x;
    const int by = blockIdx.y;
    const int kz = blockIdx.z;
    const int tid = threadIdx.x;
    const int tx = tid & 15;
    const int ty = tid >> 4;

    const int arow = tid >> 2;
    const int acol = (tid & 3) * 4;

    const float* __restrict__ aptr =
        g_res + ((size_t)(by * GBM + arow)) * KIN + kz * KQ + acol;
    const float* __restrict__ bptr =
        Wt    + ((size_t)(bx * GBN + arow)) * KIN + kz * KQ + acol;

    float4 fa = *(const float4*)aptr;
    float4 fb = *(const float4*)bptr;

    As[0][acol + 0][arow] = fa.x;
    As[0][acol + 1][arow] = fa.y;
    As[0][acol + 2][arow] = fa.z;
    As[0][acol + 3][arow] = fa.w;
    Bs[0][acol + 0][arow] = fb.x;
    Bs[0][acol + 1][arow] = fb.y;
    Bs[0][acol + 2][arow] = fb.z;
    Bs[0][acol + 3][arow] = fb.w;
    __syncthreads();

    float acc[4][4] = {};
    int buf = 0;

    for (int k0 = GBK; k0 <= KQ; k0 += GBK) {
        const bool more = (k0 < KQ);
        if (more) {
            fa = *(const float4*)(aptr + k0);
            fb = *(const float4*)(bptr + k0);
        }

        #pragma unroll
        for (int k = 0; k < GBK; ++k) {
            const float4 av = *(const float4*)&As[buf][k][ty * 4];
            const float4 bv = *(const float4*)&Bs[buf][k][tx * 4];
            acc[0][0] += av.x * bv.x; acc[0][1] += av.x * bv.y;
            acc[0][2] += av.x * bv.z; acc[0][3] += av.x * bv.w;
            acc[1][0] += av.y * bv.x; acc[1][1] += av.y * bv.y;
            acc[1][2] += av.y * bv.z; acc[1][3] += av.y * bv.w;
            acc[2][0] += av.z * bv.x; acc[2][1] += av.z * bv.y;
            acc[2][2] += av.z * bv.z; acc[2][3] += av.z * bv.w;
            acc[3][0] += av.w * bv.x; acc[3][1] += av.w * bv.y;
            acc[3][2] += av.w * bv.z; acc[3][3] += av.w * bv.w;
        }

        if (more) {
            const int nb = buf ^ 1;
            As[nb][acol + 0][arow] = fa.x;
            As[nb][acol + 1][arow] = fa.y;
            As[nb][acol + 2][arow] = fa.z;
            As[nb][acol + 3][arow] = fa.w;
            Bs[nb][acol + 0][arow] = fb.x;
            Bs[nb][acol + 1][arow] = fb.y;
            Bs[nb][acol + 2][arow] = fb.z;
            Bs[nb][acol + 3][arow] = fb.w;
        }
        __syncthreads();
        buf ^= 1;
    }

    float* __restrict__ part = g_part + (size_t)kz * BSZ * OUTD;
    const int orow = by * GBM + ty * 4;
    const int ocol = bx * GBN + tx * 4;
    #pragma unroll
    for (int i = 0; i < 4; ++i) {
        float4 o;
        o.x = acc[i][0]; o.y = acc[i][1]; o.z = acc[i][2]; o.w = acc[i][3];
        *(float4*)(part + (size_t)(orow + i) * OUTD + ocol) = o;
    }
}

// ---------------------------------------------------------------------------
// Kernel C: out = sum(part[0..3]) + bias
// ---------------------------------------------------------------------------
__global__ __launch_bounds__(256) void dnd_reduce_kernel(
    const float* __restrict__ bias,
    float* __restrict__ out)
{
    const int i = blockIdx.x * 256 + threadIdx.x;
    const size_t stride4 = (size_t)BSZ * OUTD / 4;
    const float4 a = ((const float4*)g_part)[i];
    const float4 c = ((const float4*)g_part)[i + stride4];
    const float4 d = ((const float4*)g_part)[i + 2 * stride4];
    const float4 e = ((const float4*)g_part)[i + 3 * stride4];
    const float4 bz = ((const float4*)bias)[i & (OUTD / 4 - 1)];
    float4 o;
    o.x = a.x + c.x + d.x + e.x + bz.x;
    o.y = a.y + c.y + d.y + e.y + bz.y;
    o.z = a.z + c.z + d.z + e.z + bz.z;
    o.w = a.w + c.w + d.w + e.w + bz.w;
    ((float4*)out)[i] = o;
}

// ---------------------------------------------------------------------------
// Launch
// ---------------------------------------------------------------------------
extern "C" void kernel_launch(void* const* d_in, const int* in_sizes, int n_in,
                              void* d_out, int out_size)
{
    const float* keys  = (const float*)d_in[0];
    const float* vals  = (const float*)d_in[1];
    const float* rpe   = (const float*)d_in[2];
    const float* query = (const float*)d_in[3];
    const float* W     = (const float*)d_in[4];
    const float* bias  = (const float*)d_in[5];
    const int*   mstep = (const int*)d_in[6];

    float* out = (float*)d_out;

    dnd_weights_kernel<<<BSZ, 256>>>(keys, rpe, query, mstep);

    dnd_apply_kernel<<<BSZ, 128>>>(vals, mstep);

    dim3 ggrid(OUTD / GBN, BSZ / GBM, KSPLIT);    // (8, 16, 4)
    dnd_gemm_kernel<<<ggrid, 256>>>(W);

    dnd_reduce_kernel<<<(BSZ * OUTD / 4) / 256, 256>>>(bias, out);
}

// round 8
// speedup vs baseline: 1.4504x; 1.0177x over previous
#include <cuda_runtime.h>
#include <cstdint>

// Problem constants: T=512, B=1024, DK=128, H=256, NH=4
#define T_MAX 512
#define BSZ   1024
#define DKDIM 128
#define VDIM  512      // 2*H
#define NHEAD 4
#define OUTD  512      // 2*H
#define KIN   2048     // NH*2*H

// scratch: weights [B][NH][T] (8MB), res [B][KIN] (8MB), split-K partials (8MB)
__device__ float g_w[(size_t)BSZ * NHEAD * T_MAX];
__device__ float g_res[(size_t)BSZ * KIN];
__device__ float g_part[(size_t)4 * BSZ * OUTD];

// streaming float4 load (evict-first: data has zero reuse)
static __device__ __forceinline__ float4 ldcs4(const float4* p) {
    return __ldcs(p);
}

// ---------------------------------------------------------------------------
// Kernel A1: logits + softmax -> normalized weights g_w[b][n][m]
// One CTA per batch element. 256 threads.
// ---------------------------------------------------------------------------
__global__ __launch_bounds__(256) void dnd_weights_kernel(
    const float* __restrict__ keys,   // [T][B][DK]
    const float* __restrict__ rpe,    // [T][B]
    const float* __restrict__ query,  // [B][NH][DK]
    const int*   __restrict__ min_step_p)
{
    __shared__ __align__(16) float sQ[NHEAD * DKDIM];     // 2 KB
    __shared__ __align__(16) float sA[NHEAD][T_MAX];      // 8 KB

    const int b    = blockIdx.x;
    const int tid  = threadIdx.x;
    const int warp = tid >> 5;
    const int lane = tid & 31;
    const int M    = min_step_p[0];

    for (int i = tid; i < NHEAD * DKDIM; i += 256)
        sQ[i] = query[(size_t)b * NHEAD * DKDIM + i];
    __syncthreads();

    // phase 1: 8 lanes per head (lane = h*8+j); 2 slots per warp iteration.
    {
        const int h = lane >> 3;
        const int j = lane & 7;
        float4 q4[4];
        #pragma unroll
        for (int it = 0; it < 4; ++it)
            q4[it] = ((const float4*)sQ)[h * 32 + it * 8 + j];

        const int Mfull = M & ~15;
        for (int m = warp; m < Mfull; m += 16) {
            const int m1 = m + 8;
            const float4* __restrict__ ka =
                (const float4*)(keys + ((size_t)m  * BSZ + b) * DKDIM);
            const float4* __restrict__ kb =
                (const float4*)(keys + ((size_t)m1 * BSZ + b) * DKDIM);
            float4 la[4], lb[4];
            #pragma unroll
            for (int it = 0; it < 4; ++it) { la[it] = ldcs4(ka + it * 8 + j); }
            #pragma unroll
            for (int it = 0; it < 4; ++it) { lb[it] = ldcs4(kb + it * 8 + j); }
            float pa = 0.0f, pb = 0.0f;
            #pragma unroll
            for (int it = 0; it < 4; ++it) {
                pa += la[it].x * q4[it].x + la[it].y * q4[it].y
                    + la[it].z * q4[it].z + la[it].w * q4[it].w;
                pb += lb[it].x * q4[it].x + lb[it].y * q4[it].y
                    + lb[it].z * q4[it].z + lb[it].w * q4[it].w;
            }
            pa += __shfl_down_sync(0xffffffffu, pa, 4);
            pb += __shfl_down_sync(0xffffffffu, pb, 4);
            pa += __shfl_down_sync(0xffffffffu, pa, 2);
            pb += __shfl_down_sync(0xffffffffu, pb, 2);
            pa += __shfl_down_sync(0xffffffffu, pa, 1);
            pb += __shfl_down_sync(0xffffffffu, pb, 1);
            if (j == 0) {
                sA[h][m]  = pa * __ldg(&rpe[(size_t)m  * BSZ + b]);
                sA[h][m1] = pb * __ldg(&rpe[(size_t)m1 * BSZ + b]);
            }
        }
        for (int m = Mfull + warp; m < M; m += 8) {
            const float4* __restrict__ krow =
                (const float4*)(keys + ((size_t)m * BSZ + b) * DKDIM);
            float p = 0.0f;
            #pragma unroll
            for (int it = 0; it < 4; ++it) {
                const float4 k4 = ldcs4(krow + it * 8 + j);
                p += k4.x * q4[it].x + k4.y * q4[it].y
                   + k4.z * q4[it].z + k4.w * q4[it].w;
            }
            p += __shfl_down_sync(0xffffffffu, p, 4);
            p += __shfl_down_sync(0xffffffffu, p, 2);
            p += __shfl_down_sync(0xffffffffu, p, 1);
            if (j == 0)
                sA[h][m] = p * __ldg(&rpe[(size_t)m * BSZ + b]);
        }
    }
    __syncthreads();

    // phase 2: softmax per head (one warp per head)
    if (warp < NHEAD) {
        float* a = sA[warp];
        float mx = -1e30f;
        for (int m = lane; m < M; m += 32) mx = fmaxf(mx, a[m]);
        #pragma unroll
        for (int off = 16; off > 0; off >>= 1)
            mx = fmaxf(mx, __shfl_xor_sync(0xffffffffu, mx, off));
        float s = 0.0f;
        for (int m = lane; m < M; m += 32) {
            float e = __expf(a[m] - mx);
            a[m] = e;
            s += e;
        }
        #pragma unroll
        for (int off = 16; off > 0; off >>= 1)
            s += __shfl_xor_sync(0xffffffffu, s, off);
        const float inv = 1.0f / s;
        for (int m = lane; m < M; m += 32) a[m] *= inv;
    }
    __syncthreads();

    // write weights
    {
        const float4* sA4 = (const float4*)&sA[0][0];
        float4* w4 = (float4*)(g_w + (size_t)b * NHEAD * T_MAX);
        #pragma unroll
        for (int i = 0; i < 2; ++i)
            w4[tid + 256 * i] = sA4[tid + 256 * i];
    }
}

// ---------------------------------------------------------------------------
// Kernel A2: res[b][n][v] = sum_m w[b][n][m] * vals[m][b][v]
// One CTA per b (grid 1024), 128 threads, each thread owns 4 consecutive v.
// Streaming LDG.128, 16-slot unroll -> 256B in flight per thread.
// ---------------------------------------------------------------------------
__global__ __launch_bounds__(128) void dnd_apply_kernel(
    const float* __restrict__ vals,   // [T][B][VDIM]
    const int*   __restrict__ min_step_p)
{
    __shared__ __align__(16) float sW[NHEAD][T_MAX];   // 8 KB

    const int b   = blockIdx.x;
    const int tid = threadIdx.x;    // 0..127
    const int M   = min_step_p[0];

    // stage weights
    {
        const float4* w4 = (const float4*)(g_w + (size_t)b * NHEAD * T_MAX);
        float4* s4 = (float4*)&sW[0][0];
        #pragma unroll
        for (int i = 0; i < 4; ++i)
            s4[tid + 128 * i] = w4[tid + 128 * i];
    }
    __syncthreads();

    float acc[NHEAD][4] = {};
    const float4* __restrict__ V4 = (const float4*)vals;
    const size_t rowstride = (size_t)BSZ * (VDIM / 4);   // float4 units per m
    const size_t base = (size_t)b * (VDIM / 4) + tid;

    const int M16 = M & ~15;
    for (int m0 = 0; m0 < M16; m0 += 16) {
        float4 v[16];
        #pragma unroll
        for (int u = 0; u < 16; ++u)
            v[u] = ldcs4(V4 + base + (size_t)(m0 + u) * rowstride);

        #pragma unroll
        for (int half = 0; half < 2; ++half) {
            const int mh = m0 + half * 8;
            #pragma unroll
            for (int n = 0; n < NHEAD; ++n) {
                const float4 wa = *(const float4*)&sW[n][mh];
                const float4 wb = *(const float4*)&sW[n][mh + 4];
                const float4* vv = &v[half * 8];
                acc[n][0] += wa.x * vv[0].x; acc[n][1] += wa.x * vv[0].y;
                acc[n][2] += wa.x * vv[0].z; acc[n][3] += wa.x * vv[0].w;
                acc[n][0] += wa.y * vv[1].x; acc[n][1] += wa.y * vv[1].y;
                acc[n][2] += wa.y * vv[1].z; acc[n][3] += wa.y * vv[1].w;
                acc[n][0] += wa.z * vv[2].x; acc[n][1] += wa.z * vv[2].y;
                acc[n][2] += wa.z * vv[2].z; acc[n][3] += wa.z * vv[2].w;
                acc[n][0] += wa.w * vv[3].x; acc[n][1] += wa.w * vv[3].y;
                acc[n][2] += wa.w * vv[3].z; acc[n][3] += wa.w * vv[3].w;
                acc[n][0] += wb.x * vv[4].x; acc[n][1] += wb.x * vv[4].y;
                acc[n][2] += wb.x * vv[4].z; acc[n][3] += wb.x * vv[4].w;
                acc[n][0] += wb.y * vv[5].x; acc[n][1] += wb.y * vv[5].y;
                acc[n][2] += wb.y * vv[5].z; acc[n][3] += wb.y * vv[5].w;
                acc[n][0] += wb.z * vv[6].x; acc[n][1] += wb.z * vv[6].y;
                acc[n][2] += wb.z * vv[6].z; acc[n][3] += wb.z * vv[6].w;
                acc[n][0] += wb.w * vv[7].x; acc[n][1] += wb.w * vv[7].y;
                acc[n][2] += wb.w * vv[7].z; acc[n][3] += wb.w * vv[7].w;
            }
        }
    }
    for (int m = M16; m < M; ++m) {
        const float4 v = ldcs4(V4 + base + (size_t)m * rowstride);
        #pragma unroll
        for (int n = 0; n < NHEAD; ++n) {
            const float w = sW[n][m];
            acc[n][0] += w * v.x; acc[n][1] += w * v.y;
            acc[n][2] += w * v.z; acc[n][3] += w * v.w;
        }
    }

    const int v0 = 4 * tid;
    #pragma unroll
    for (int n = 0; n < NHEAD; ++n) {
        float4 o;
        o.x = acc[n][0]; o.y = acc[n][1]; o.z = acc[n][2]; o.w = acc[n][3];
        *(float4*)&g_res[((size_t)b * NHEAD + n) * VDIM + v0] = o;
    }
}

// ---------------------------------------------------------------------------
// Kernel B: split-K GEMM (K split 4). part[kz] = res[.,Kq kz] @ W[.,Kq kz]^T
// 64x64 tile, BK=16, 256 threads, 4x4/thread, double-buffered. grid (8,16,4).
// ---------------------------------------------------------------------------
#define GBM 64
#define GBN 64
#define GBK 16
#define GPAD 4
#define KSPLIT 4
#define KQ (KIN / KSPLIT)   // 512

__global__ __launch_bounds__(256) void dnd_gemm_kernel(
    const float* __restrict__ Wt)    // [OUTD][KIN]
{
    __shared__ __align__(16) float As[2][GBK][GBM + GPAD];
    __shared__ __align__(16) float Bs[2][GBK][GBN + GPAD];

    const int bx = blockIdx.x;
    const int by = blockIdx.y;
    const int kz = blockIdx.z;
    const int tid = threadIdx.x;
    const int tx = tid & 15;
    const int ty = tid >> 4;

    const int arow = tid >> 2;
    const int acol = (tid & 3) * 4;

    const float* __restrict__ aptr =
        g_res + ((size_t)(by * GBM + arow)) * KIN + kz * KQ + acol;
    const float* __restrict__ bptr =
        Wt    + ((size_t)(bx * GBN + arow)) * KIN + kz * KQ + acol;

    float4 fa = *(const float4*)aptr;
    float4 fb = *(const float4*)bptr;

    As[0][acol + 0][arow] = fa.x;
    As[0][acol + 1][arow] = fa.y;
    As[0][acol + 2][arow] = fa.z;
    As[0][acol + 3][arow] = fa.w;
    Bs[0][acol + 0][arow] = fb.x;
    Bs[0][acol + 1][arow] = fb.y;
    Bs[0][acol + 2][arow] = fb.z;
    Bs[0][acol + 3][arow] = fb.w;
    __syncthreads();

    float acc[4][4] = {};
    int buf = 0;

    for (int k0 = GBK; k0 <= KQ; k0 += GBK) {
        const bool more = (k0 < KQ);
        if (more) {
            fa = *(const float4*)(aptr + k0);
            fb = *(const float4*)(bptr + k0);
        }

        #pragma unroll
        for (int k = 0; k < GBK; ++k) {
            const float4 av = *(const float4*)&As[buf][k][ty * 4];
            const float4 bv = *(const float4*)&Bs[buf][k][tx * 4];
            acc[0][0] += av.x * bv.x; acc[0][1] += av.x * bv.y;
            acc[0][2] += av.x * bv.z; acc[0][3] += av.x * bv.w;
            acc[1][0] += av.y * bv.x; acc[1][1] += av.y * bv.y;
            acc[1][2] += av.y * bv.z; acc[1][3] += av.y * bv.w;
            acc[2][0] += av.z * bv.x; acc[2][1] += av.z * bv.y;
            acc[2][2] += av.z * bv.z; acc[2][3] += av.z * bv.w;
            acc[3][0] += av.w * bv.x; acc[3][1] += av.w * bv.y;
            acc[3][2] += av.w * bv.z; acc[3][3] += av.w * bv.w;
        }

        if (more) {
            const int nb = buf ^ 1;
            As[nb][acol + 0][arow] = fa.x;
            As[nb][acol + 1][arow] = fa.y;
            As[nb][acol + 2][arow] = fa.z;
            As[nb][acol + 3][arow] = fa.w;
            Bs[nb][acol + 0][arow] = fb.x;
            Bs[nb][acol + 1][arow] = fb.y;
            Bs[nb][acol + 2][arow] = fb.z;
            Bs[nb][acol + 3][arow] = fb.w;
        }
        __syncthreads();
        buf ^= 1;
    }

    float* __restrict__ part = g_part + (size_t)kz * BSZ * OUTD;
    const int orow = by * GBM + ty * 4;
    const int ocol = bx * GBN + tx * 4;
    #pragma unroll
    for (int i = 0; i < 4; ++i) {
        float4 o;
        o.x = acc[i][0]; o.y = acc[i][1]; o.z = acc[i][2]; o.w = acc[i][3];
        *(float4*)(part + (size_t)(orow + i) * OUTD + ocol) = o;
    }
}

// ---------------------------------------------------------------------------
// Kernel C: out = sum(part[0..3]) + bias
// ---------------------------------------------------------------------------
__global__ __launch_bounds__(256) void dnd_reduce_kernel(
    const float* __restrict__ bias,
    float* __restrict__ out)
{
    const int i = blockIdx.x * 256 + threadIdx.x;
    const size_t stride4 = (size_t)BSZ * OUTD / 4;
    const float4 a = ((const float4*)g_part)[i];
    const float4 c = ((const float4*)g_part)[i + stride4];
    const float4 d = ((const float4*)g_part)[i + 2 * stride4];
    const float4 e = ((const float4*)g_part)[i + 3 * stride4];
    const float4 bz = ((const float4*)bias)[i & (OUTD / 4 - 1)];
    float4 o;
    o.x = a.x + c.x + d.x + e.x + bz.x;
    o.y = a.y + c.y + d.y + e.y + bz.y;
    o.z = a.z + c.z + d.z + e.z + bz.z;
    o.w = a.w + c.w + d.w + e.w + bz.w;
    ((float4*)out)[i] = o;
}

// ---------------------------------------------------------------------------
// Launch
// ---------------------------------------------------------------------------
extern "C" void kernel_launch(void* const* d_in, const int* in_sizes, int n_in,
                              void* d_out, int out_size)
{
    const float* keys  = (const float*)d_in[0];
    const float* vals  = (const float*)d_in[1];
    const float* rpe   = (const float*)d_in[2];
    const float* query = (const float*)d_in[3];
    const float* W     = (const float*)d_in[4];
    const float* bias  = (const float*)d_in[5];
    const int*   mstep = (const int*)d_in[6];

    float* out = (float*)d_out;

    dnd_weights_kernel<<<BSZ, 256>>>(keys, rpe, query, mstep);

    dnd_apply_kernel<<<BSZ, 128>>>(vals, mstep);

    dim3 ggrid(OUTD / GBN, BSZ / GBM, KSPLIT);    // (8, 16, 4)
    dnd_gemm_kernel<<<ggrid, 256>>>(W);

    dnd_reduce_kernel<<<(BSZ * OUTD / 4) / 256, 256>>>(bias, out);
}

// round 9
// speedup vs baseline: 1.4510x; 1.0004x over previous
#include <cuda_runtime.h>
#include <cstdint>

// Problem constants: T=512, B=1024, DK=128, H=256, NH=4
#define T_MAX 512
#define BSZ   1024
#define DKDIM 128
#define VDIM  512      // 2*H
#define NHEAD 4
#define OUTD  512      // 2*H
#define KIN   2048     // NH*2*H

// scratch: weights [B][NH][T] (8MB), res partials [2][B][KIN] (16MB),
//          split-K partials [4][B][OUTD] (8MB)
__device__ float g_w[(size_t)BSZ * NHEAD * T_MAX];
__device__ float g_res[(size_t)2 * BSZ * KIN];
__device__ float g_part[(size_t)4 * BSZ * OUTD];

static __device__ __forceinline__ float4 ldcs4(const float4* p) {
    return __ldcs(p);
}

// ---------------------------------------------------------------------------
// Kernel A1a: raw scaled logits -> g_w[b][n][m] (no softmax)
// grid (BSZ, 2): m-halves. 256 threads.
// ---------------------------------------------------------------------------
__global__ __launch_bounds__(256) void dnd_logits_kernel(
    const float* __restrict__ keys,   // [T][B][DK]
    const float* __restrict__ rpe,    // [T][B]
    const float* __restrict__ query,  // [B][NH][DK]
    const int*   __restrict__ min_step_p)
{
    __shared__ __align__(16) float sQ[NHEAD * DKDIM];     // 2 KB

    const int b    = blockIdx.x;
    const int half = blockIdx.y;
    const int tid  = threadIdx.x;
    const int warp = tid >> 5;
    const int lane = tid & 31;
    const int M    = min_step_p[0];
    const int ms   = (M * half) >> 1;
    const int me   = (M * (half + 1)) >> 1;

    for (int i = tid; i < NHEAD * DKDIM; i += 256)
        sQ[i] = query[(size_t)b * NHEAD * DKDIM + i];
    __syncthreads();

    // 8 lanes per head: lane = h*8+j; 2 slots per warp iteration.
    const int h = lane >> 3;
    const int j = lane & 7;
    float4 q4[4];
    #pragma unroll
    for (int it = 0; it < 4; ++it)
        q4[it] = ((const float4*)sQ)[h * 32 + it * 8 + j];

    float* __restrict__ wrow = g_w + ((size_t)b * NHEAD + h) * T_MAX;

    const int span = me - ms;
    const int mend2 = ms + (span & ~15);
    for (int m = ms + warp; m < mend2; m += 16) {
        const int m1 = m + 8;
        const float4* __restrict__ ka =
            (const float4*)(keys + ((size_t)m  * BSZ + b) * DKDIM);
        const float4* __restrict__ kb =
            (const float4*)(keys + ((size_t)m1 * BSZ + b) * DKDIM);
        float4 la[4], lb[4];
        #pragma unroll
        for (int it = 0; it < 4; ++it) { la[it] = ldcs4(ka + it * 8 + j); }
        #pragma unroll
        for (int it = 0; it < 4; ++it) { lb[it] = ldcs4(kb + it * 8 + j); }
        float pa = 0.0f, pb = 0.0f;
        #pragma unroll
        for (int it = 0; it < 4; ++it) {
            pa += la[it].x * q4[it].x + la[it].y * q4[it].y
                + la[it].z * q4[it].z + la[it].w * q4[it].w;
            pb += lb[it].x * q4[it].x + lb[it].y * q4[it].y
                + lb[it].z * q4[it].z + lb[it].w * q4[it].w;
        }
        pa += __shfl_down_sync(0xffffffffu, pa, 4);
        pb += __shfl_down_sync(0xffffffffu, pb, 4);
        pa += __shfl_down_sync(0xffffffffu, pa, 2);
        pb += __shfl_down_sync(0xffffffffu, pb, 2);
        pa += __shfl_down_sync(0xffffffffu, pa, 1);
        pb += __shfl_down_sync(0xffffffffu, pb, 1);
        if (j == 0) {
            wrow[m]  = pa * __ldg(&rpe[(size_t)m  * BSZ + b]);
            wrow[m1] = pb * __ldg(&rpe[(size_t)m1 * BSZ + b]);
        }
    }
    for (int m = mend2 + warp; m < me; m += 8) {
        const float4* __restrict__ krow =
            (const float4*)(keys + ((size_t)m * BSZ + b) * DKDIM);
        float p = 0.0f;
        #pragma unroll
        for (int it = 0; it < 4; ++it) {
            const float4 k4 = ldcs4(krow + it * 8 + j);
            p += k4.x * q4[it].x + k4.y * q4[it].y
               + k4.z * q4[it].z + k4.w * q4[it].w;
        }
        p += __shfl_down_sync(0xffffffffu, p, 4);
        p += __shfl_down_sync(0xffffffffu, p, 2);
        p += __shfl_down_sync(0xffffffffu, p, 1);
        if (j == 0)
            wrow[m] = p * __ldg(&rpe[(size_t)m * BSZ + b]);
    }
}

// ---------------------------------------------------------------------------
// Kernel A1b: in-place softmax over g_w[b][n][0..M). grid BSZ, 128 thr.
// Each warp owns one head row, held entirely in 16 registers.
// ---------------------------------------------------------------------------
__global__ __launch_bounds__(128) void dnd_softmax_kernel(
    const int* __restrict__ min_step_p)
{
    const int b    = blockIdx.x;
    const int warp = threadIdx.x >> 5;   // head
    const int lane = threadIdx.x & 31;
    const int M    = min_step_p[0];

    float* __restrict__ row = g_w + ((size_t)b * NHEAD + warp) * T_MAX;

    float v[16];
    #pragma unroll
    for (int i = 0; i < 16; ++i) {
        const int m = lane + 32 * i;
        v[i] = (m < M) ? row[m] : -1e30f;
    }
    float mx = -1e30f;
    #pragma unroll
    for (int i = 0; i < 16; ++i) mx = fmaxf(mx, v[i]);
    #pragma unroll
    for (int off = 16; off > 0; off >>= 1)
        mx = fmaxf(mx, __shfl_xor_sync(0xffffffffu, mx, off));
    float s = 0.0f;
    #pragma unroll
    for (int i = 0; i < 16; ++i) {
        v[i] = __expf(v[i] - mx);
        s += v[i];
    }
    #pragma unroll
    for (int off = 16; off > 0; off >>= 1)
        s += __shfl_xor_sync(0xffffffffu, s, off);
    const float inv = 1.0f / s;
    #pragma unroll
    for (int i = 0; i < 16; ++i) {
        const int m = lane + 32 * i;
        if (m < M) row[m] = v[i] * inv;
    }
}

// ---------------------------------------------------------------------------
// Kernel A2: partial res over an m-half.
// grid (BSZ, 2). 128 threads, thread owns 4 consecutive v. 8-slot unroll.
// g_res[half][b][n][v]
// ---------------------------------------------------------------------------
__global__ __launch_bounds__(128) void dnd_apply_kernel(
    const float* __restrict__ vals,   // [T][B][VDIM]
    const int*   __restrict__ min_step_p)
{
    __shared__ __align__(16) float sW[NHEAD][T_MAX];   // 8 KB

    const int b    = blockIdx.x;
    const int half = blockIdx.y;
    const int tid  = threadIdx.x;    // 0..127
    const int M    = min_step_p[0];
    const int ms   = (M * half) >> 1;
    const int me   = (M * (half + 1)) >> 1;

    // stage weights (full rows; only [ms,me) used)
    {
        const float4* w4 = (const float4*)(g_w + (size_t)b * NHEAD * T_MAX);
        float4* s4 = (float4*)&sW[0][0];
        #pragma unroll
        for (int i = 0; i < 4; ++i)
            s4[tid + 128 * i] = w4[tid + 128 * i];
    }
    __syncthreads();

    float acc[NHEAD][4] = {};
    const float4* __restrict__ V4 = (const float4*)vals;
    const size_t rowstride = (size_t)BSZ * (VDIM / 4);
    const size_t base = (size_t)b * (VDIM / 4) + tid;

    const int span = me - ms;
    const int mend = ms + (span & ~7);
    for (int m0 = ms; m0 < mend; m0 += 8) {
        float4 v[8];
        #pragma unroll
        for (int u = 0; u < 8; ++u)
            v[u] = ldcs4(V4 + base + (size_t)(m0 + u) * rowstride);

        #pragma unroll
        for (int n = 0; n < NHEAD; ++n) {
            const float4 wa = *(const float4*)&sW[n][m0];
            const float4 wb = *(const float4*)&sW[n][m0 + 4];
            acc[n][0] += wa.x * v[0].x; acc[n][1] += wa.x * v[0].y;
            acc[n][2] += wa.x * v[0].z; acc[n][3] += wa.x * v[0].w;
            acc[n][0] += wa.y * v[1].x; acc[n][1] += wa.y * v[1].y;
            acc[n][2] += wa.y * v[1].z; acc[n][3] += wa.y * v[1].w;
            acc[n][0] += wa.z * v[2].x; acc[n][1] += wa.z * v[2].y;
            acc[n][2] += wa.z * v[2].z; acc[n][3] += wa.z * v[2].w;
            acc[n][0] += wa.w * v[3].x; acc[n][1] += wa.w * v[3].y;
            acc[n][2] += wa.w * v[3].z; acc[n][3] += wa.w * v[3].w;
            acc[n][0] += wb.x * v[4].x; acc[n][1] += wb.x * v[4].y;
            acc[n][2] += wb.x * v[4].z; acc[n][3] += wb.x * v[4].w;
            acc[n][0] += wb.y * v[5].x; acc[n][1] += wb.y * v[5].y;
            acc[n][2] += wb.y * v[5].z; acc[n][3] += wb.y * v[5].w;
            acc[n][0] += wb.z * v[6].x; acc[n][1] += wb.z * v[6].y;
            acc[n][2] += wb.z * v[6].z; acc[n][3] += wb.z * v[6].w;
            acc[n][0] += wb.w * v[7].x; acc[n][1] += wb.w * v[7].y;
            acc[n][2] += wb.w * v[7].z; acc[n][3] += wb.w * v[7].w;
        }
    }
    for (int m = mend; m < me; ++m) {
        const float4 v = ldcs4(V4 + base + (size_t)m * rowstride);
        #pragma unroll
        for (int n = 0; n < NHEAD; ++n) {
            const float w = sW[n][m];
            acc[n][0] += w * v.x; acc[n][1] += w * v.y;
            acc[n][2] += w * v.z; acc[n][3] += w * v.w;
        }
    }

    float* __restrict__ rdst = g_res + (size_t)half * BSZ * KIN;
    const int v0 = 4 * tid;
    #pragma unroll
    for (int n = 0; n < NHEAD; ++n) {
        float4 o;
        o.x = acc[n][0]; o.y = acc[n][1]; o.z = acc[n][2]; o.w = acc[n][3];
        *(float4*)&rdst[((size_t)b * NHEAD + n) * VDIM + v0] = o;
    }
}

// ---------------------------------------------------------------------------
// Kernel B: split-K GEMM (K split 4), A = sum of the two res partials.
// 64x64 tile, BK=16, 256 threads, 4x4/thread, double-buffered. grid (8,16,4).
// ---------------------------------------------------------------------------
#define GBM 64
#define GBN 64
#define GBK 16
#define GPAD 4
#define KSPLIT 4
#define KQ (KIN / KSPLIT)   // 512

__global__ __launch_bounds__(256) void dnd_gemm_kernel(
    const float* __restrict__ Wt)    // [OUTD][KIN]
{
    __shared__ __align__(16) float As[2][GBK][GBM + GPAD];
    __shared__ __align__(16) float Bs[2][GBK][GBN + GPAD];

    const int bx = blockIdx.x;
    const int by = blockIdx.y;
    const int kz = blockIdx.z;
    const int tid = threadIdx.x;
    const int tx = tid & 15;
    const int ty = tid >> 4;

    const int arow = tid >> 2;
    const int acol = (tid & 3) * 4;

    const float* __restrict__ aptr0 =
        g_res + ((size_t)(by * GBM + arow)) * KIN + kz * KQ + acol;
    const float* __restrict__ aptr1 = aptr0 + (size_t)BSZ * KIN;
    const float* __restrict__ bptr =
        Wt    + ((size_t)(bx * GBN + arow)) * KIN + kz * KQ + acol;

    float4 fa0 = *(const float4*)aptr0;
    float4 fa1 = *(const float4*)aptr1;
    float4 fb  = *(const float4*)bptr;

    As[0][acol + 0][arow] = fa0.x + fa1.x;
    As[0][acol + 1][arow] = fa0.y + fa1.y;
    As[0][acol + 2][arow] = fa0.z + fa1.z;
    As[0][acol + 3][arow] = fa0.w + fa1.w;
    Bs[0][acol + 0][arow] = fb.x;
    Bs[0][acol + 1][arow] = fb.y;
    Bs[0][acol + 2][arow] = fb.z;
    Bs[0][acol + 3][arow] = fb.w;
    __syncthreads();

    float acc[4][4] = {};
    int buf = 0;

    for (int k0 = GBK; k0 <= KQ; k0 += GBK) {
        const bool more = (k0 < KQ);
        if (more) {
            fa0 = *(const float4*)(aptr0 + k0);
            fa1 = *(const float4*)(aptr1 + k0);
            fb  = *(const float4*)(bptr + k0);
        }

        #pragma unroll
        for (int k = 0; k < GBK; ++k) {
            const float4 av = *(const float4*)&As[buf][k][ty * 4];
            const float4 bv = *(const float4*)&Bs[buf][k][tx * 4];
            acc[0][0] += av.x * bv.x; acc[0][1] += av.x * bv.y;
            acc[0][2] += av.x * bv.z; acc[0][3] += av.x * bv.w;
            acc[1][0] += av.y * bv.x; acc[1][1] += av.y * bv.y;
            acc[1][2] += av.y * bv.z; acc[1][3] += av.y * bv.w;
            acc[2][0] += av.z * bv.x; acc[2][1] += av.z * bv.y;
            acc[2][2] += av.z * bv.z; acc[2][3] += av.z * bv.w;
            acc[3][0] += av.w * bv.x; acc[3][1] += av.w * bv.y;
            acc[3][2] += av.w * bv.z; acc[3][3] += av.w * bv.w;
        }

        if (more) {
            const int nb = buf ^ 1;
            As[nb][acol + 0][arow] = fa0.x + fa1.x;
            As[nb][acol + 1][arow] = fa0.y + fa1.y;
            As[nb][acol + 2][arow] = fa0.z + fa1.z;
            As[nb][acol + 3][arow] = fa0.w + fa1.w;
            Bs[nb][acol + 0][arow] = fb.x;
            Bs[nb][acol + 1][arow] = fb.y;
            Bs[nb][acol + 2][arow] = fb.z;
            Bs[nb][acol + 3][arow] = fb.w;
        }
        __syncthreads();
        buf ^= 1;
    }

    float* __restrict__ part = g_part + (size_t)kz * BSZ * OUTD;
    const int orow = by * GBM + ty * 4;
    const int ocol = bx * GBN + tx * 4;
    #pragma unroll
    for (int i = 0; i < 4; ++i) {
        float4 o;
        o.x = acc[i][0]; o.y = acc[i][1]; o.z = acc[i][2]; o.w = acc[i][3];
        *(float4*)(part + (size_t)(orow + i) * OUTD + ocol) = o;
    }
}

// ---------------------------------------------------------------------------
// Kernel C: out = sum(part[0..3]) + bias
// ---------------------------------------------------------------------------
__global__ __launch_bounds__(256) void dnd_reduce_kernel(
    const float* __restrict__ bias,
    float* __restrict__ out)
{
    const int i = blockIdx.x * 256 + threadIdx.x;
    const size_t stride4 = (size_t)BSZ * OUTD / 4;
    const float4 a = ((const float4*)g_part)[i];
    const float4 c = ((const float4*)g_part)[i + stride4];
    const float4 d = ((const float4*)g_part)[i + 2 * stride4];
    const float4 e = ((const float4*)g_part)[i + 3 * stride4];
    const float4 bz = ((const float4*)bias)[i & (OUTD / 4 - 1)];
    float4 o;
    o.x = a.x + c.x + d.x + e.x + bz.x;
    o.y = a.y + c.y + d.y + e.y + bz.y;
    o.z = a.z + c.z + d.z + e.z + bz.z;
    o.w = a.w + c.w + d.w + e.w + bz.w;
    ((float4*)out)[i] = o;
}

// ---------------------------------------------------------------------------
// Launch
// ---------------------------------------------------------------------------
extern "C" void kernel_launch(void* const* d_in, const int* in_sizes, int n_in,
                              void* d_out, int out_size)
{
    const float* keys  = (const float*)d_in[0];
    const float* vals  = (const float*)d_in[1];
    const float* rpe   = (const float*)d_in[2];
    const float* query = (const float*)d_in[3];
    const float* W     = (const float*)d_in[4];
    const float* bias  = (const float*)d_in[5];
    const int*   mstep = (const int*)d_in[6];

    float* out = (float*)d_out;

    dim3 lgrid(BSZ, 2);
    dnd_logits_kernel<<<lgrid, 256>>>(keys, rpe, query, mstep);

    dnd_softmax_kernel<<<BSZ, 128>>>(mstep);

    dim3 agrid(BSZ, 2);
    dnd_apply_kernel<<<agrid, 128>>>(vals, mstep);

    dim3 ggrid(OUTD / GBN, BSZ / GBM, KSPLIT);    // (8, 16, 4)
    dnd_gemm_kernel<<<ggrid, 256>>>(W);

    dnd_reduce_kernel<<<(BSZ * OUTD / 4) / 256, 256>>>(bias, out);
}